// round 13
// baseline (speedup 1.0000x reference)
#include <cuda_runtime.h>
#include <cuda_fp16.h>
#include <math.h>
#include <stdint.h>

#define NB 4
#define NS 1024
#define NE 2048
#define NH 16
#define ND 128
#define ATTN_SCALE 0.08838834764831845f

typedef __half hf;

// ---------------- scratch (device globals; referenced ONLY from device code) --
__device__ __align__(256) hf g_xh [(size_t)NB*NS*NE];
__device__ __align__(256) hf g_xl [(size_t)NB*NS*NE];
__device__ __align__(256) hf g_wih[(size_t)3*NE*NE];
__device__ __align__(256) hf g_woh[(size_t)NE*NE];
__device__ __align__(256) hf g_qh [(size_t)NB*NH*NS*ND];
__device__ __align__(256) hf g_ql [(size_t)NB*NH*NS*ND];
__device__ __align__(256) hf g_kh [(size_t)NB*NH*NS*ND];
__device__ __align__(256) hf g_vTh[(size_t)NB*NH*ND*NS];   // [b,h,d,s]
__device__ __align__(256) hf g_ch [(size_t)NB*NS*NE];
__device__ __align__(256) hf g_cl [(size_t)NB*NS*NE];

// ---------------- PTX helpers ------------------------------------------------
__device__ __forceinline__ uint32_t smem_u32(const void* p) {
    uint32_t a;
    asm("{ .reg .u64 t; cvta.to.shared.u64 t, %1; cvt.u32.u64 %0, t; }" : "=r"(a) : "l"(p));
    return a;
}

#define CP16(dst, src) \
    asm volatile("cp.async.cg.shared.global [%0], [%1], 16;" :: "r"(dst), "l"(src) : "memory")
#define CP_COMMIT() asm volatile("cp.async.commit_group;" ::: "memory")
#define CP_WAIT1()  asm volatile("cp.async.wait_group 1;" ::: "memory")
#define CP_WAIT0()  asm volatile("cp.async.wait_group 0;" ::: "memory")

__device__ __forceinline__ void ldsm4(uint32_t* r, uint32_t a) {
    asm volatile("ldmatrix.sync.aligned.m8n8.x4.shared.b16 {%0,%1,%2,%3}, [%4];"
                 : "=r"(r[0]), "=r"(r[1]), "=r"(r[2]), "=r"(r[3]) : "r"(a));
}
__device__ __forceinline__ void mma16816(float* d, const uint32_t* a, uint32_t b0, uint32_t b1) {
    asm volatile(
        "mma.sync.aligned.m16n8k16.row.col.f32.f16.f16.f32 "
        "{%0,%1,%2,%3}, {%4,%5,%6,%7}, {%8,%9}, {%0,%1,%2,%3};"
        : "+f"(d[0]), "+f"(d[1]), "+f"(d[2]), "+f"(d[3])
        : "r"(a[0]), "r"(a[1]), "r"(a[2]), "r"(a[3]), "r"(b0), "r"(b1));
}

__device__ __forceinline__ uint32_t pk(hf a, hf b) {
    return (uint32_t)__half_as_ushort(a) | ((uint32_t)__half_as_ushort(b) << 16);
}
__device__ __forceinline__ void split(float v, hf& h, hf& l) {
    h = __float2half_rn(v);
    l = __float2half_rn(v - __half2float(h));
}

// ---------------- operand-source / epilogue param structs -------------------
struct PQkv {
    const float* bias;
    __device__ const hf* ptr(int w, int) const {
        return w == 0 ? g_xh : w == 1 ? g_xl : g_wih;
    }
    __device__ __forceinline__ void store2(int, int m, int n, float v0, float v1) const {
        v0 += bias[n]; v1 += bias[n + 1];
        const int which = n >> 11;
        const int e = n & 2047, h = e >> 7, d = e & 127;
        const int b = m >> 10, s = m & 1023;
        if (which == 0) {                       // Q: split (A of S-GEMM)
            hf h0, l0, h1, l1;
            split(v0, h0, l0); split(v1, h1, l1);
            const size_t off = ((size_t)((b * NH + h) * NS + s)) * ND + d;
            *(uint32_t*)(g_qh + off) = pk(h0, h1);
            *(uint32_t*)(g_ql + off) = pk(l0, l1);
        } else if (which == 1) {                // K: hi only
            const size_t off = ((size_t)((b * NH + h) * NS + s)) * ND + d;
            *(uint32_t*)(g_kh + off) = pk(__float2half_rn(v0), __float2half_rn(v1));
        } else {                                // V: hi only, transposed [d][s]
            const size_t off = ((size_t)((b * NH + h) * ND + d)) * NS + s;
            g_vTh[off]      = __float2half_rn(v0);
            g_vTh[off + NS] = __float2half_rn(v1);
        }
    }
};

struct POut {
    const float* bias;
    float* out;
    __device__ const hf* ptr(int w, int) const {
        return w == 0 ? g_ch : w == 1 ? g_cl : g_woh;
    }
    __device__ __forceinline__ void store2(int, int m, int n, float v0, float v1) const {
        float2 o = make_float2(v0 + bias[n], v1 + bias[n + 1]);
        *(float2*)(out + (size_t)m * NE + n) = o;
    }
};

// ---------------- fp16 A-split MMA GEMM (projections) -------------------------
// C[128,128] = Ah·Bh^T + Al·Bh^T, fp32 accum. BK=32.
// 3 slots/stage (Ah, Al, Bh) x 80B pitch = 30KB/stage; THREE stages (90KB,
// 2 CTAs/SM). ONE sync per chunk, wait_group 1 (pipe never drains).
// Prefetch issued at TOP: sync at iter c proves stage (c+2)%3's readers
// (iter c-1) finished, so issue(c+2) may precede the MMA block, giving the
// load two full compute blocks to land. (R12 lesson: keeping >=1 group in
// flight beats halving barrier count.)
#define SLOT2  10240u
#define STG2   30720u
#define GSMEM  (3 * 30720)

template <class P>
__global__ __launch_bounds__(256, 2) void gemm_mma(P p, int K)
{
    extern __shared__ __align__(1024) char gsm[];
    const uint32_t sb = smem_u32(gsm);
    const int tid  = threadIdx.x;
    const int lane = tid & 31, wid = tid >> 5;
    const int wm = wid >> 1, wn = wid & 1;       // 4x2 warp grid, warp tile 32x64
    const int gid = lane >> 2, tig = lane & 3;
    const int bz = blockIdx.z;
    const int m0 = blockIdx.y * 128, n0 = blockIdx.x * 128;

    const hf* ah_p = p.ptr(0, bz);
    const hf* al_p = p.ptr(1, bz);
    const hf* bh_p = p.ptr(2, bz);

    auto issue = [&](int st, int kt) {
        const uint32_t s = sb + (uint32_t)st * STG2;
#pragma unroll
        for (int i = 0; i < 2; ++i) {
            const int idx = tid + i * 256;
            const int r = idx >> 2, c = idx & 3;
            const uint32_t d = (uint32_t)(r * 80 + c * 16);
            const size_t  o = (size_t)r * K + kt + c * 8;
            CP16(s + d,             ah_p + (size_t)m0 * K + o);
            CP16(s + SLOT2 + d,     al_p + (size_t)m0 * K + o);
            CP16(s + 2 * SLOT2 + d, bh_p + (size_t)n0 * K + o);
        }
    };

    uint32_t a_off[2], b_off[4];
#pragma unroll
    for (int mi = 0; mi < 2; ++mi)
        a_off[mi] = (uint32_t)((wm * 32 + mi * 16 + (lane & 15)) * 80 + (lane >> 4) * 16);
#pragma unroll
    for (int nb = 0; nb < 4; ++nb) {
        const int rw = wn * 64 + nb * 16 + (lane & 7) + ((lane >> 4) & 1) * 8;
        b_off[nb] = (uint32_t)(rw * 80 + ((lane >> 3) & 1) * 16);
    }

    float acc[2][8][4];
#pragma unroll
    for (int i = 0; i < 2; ++i)
#pragma unroll
        for (int j = 0; j < 8; ++j)
#pragma unroll
            for (int q = 0; q < 4; ++q) acc[i][j][q] = 0.0f;

    issue(0, 0);      CP_COMMIT();
    issue(1, 32);     CP_COMMIT();

    const int NC = K >> 5;
    int cs = 0;       // c % 3
    int ws = 2;       // (c+2) % 3
    for (int c = 0; c < NC; ++c) {
        if (c + 1 < NC) CP_WAIT1(); else CP_WAIT0();
        __syncthreads();
        if (c + 2 < NC) { issue(ws, (c + 2) << 5); CP_COMMIT(); }

        const uint32_t s = sb + (uint32_t)cs * STG2;
#pragma unroll
        for (int kh = 0; kh < 2; ++kh) {
            const uint32_t ka = kh * 32;

            uint32_t ah[2][4], al[2][4];
#pragma unroll
            for (int mi = 0; mi < 2; ++mi) {
                ldsm4(ah[mi], s + a_off[mi] + ka);
                ldsm4(al[mi], s + SLOT2 + a_off[mi] + ka);
            }
#pragma unroll
            for (int nb = 0; nb < 4; ++nb) {
                uint32_t bh[4];
                ldsm4(bh, s + 2 * SLOT2 + b_off[nb] + ka);
#pragma unroll
                for (int mi = 0; mi < 2; ++mi) {
                    mma16816(acc[mi][nb * 2],     ah[mi], bh[0], bh[1]);
                    mma16816(acc[mi][nb * 2 + 1], ah[mi], bh[2], bh[3]);
                    mma16816(acc[mi][nb * 2],     al[mi], bh[0], bh[1]);
                    mma16816(acc[mi][nb * 2 + 1], al[mi], bh[2], bh[3]);
                }
            }
        }

        if (++cs == 3) cs = 0;
        if (++ws == 3) ws = 0;
    }

#pragma unroll
    for (int mi = 0; mi < 2; ++mi)
#pragma unroll
        for (int nf = 0; nf < 8; ++nf) {
            const int m = m0 + wm * 32 + mi * 16 + gid;
            const int n = n0 + wn * 64 + nf * 8 + tig * 2;
            p.store2(bz, m,     n, acc[mi][nf][0], acc[mi][nf][1]);
            p.store2(bz, m + 8, n, acc[mi][nf][2], acc[mi][nf][3]);
        }
}

// ---------------- fused flash attention (fp16, A-split, 3-stage, top-issue) ---
#define KH_OFF 0u
#define VH_OFF 17408u
#define FSTAGE 35840u
#define FSMEM  (3 * 35840)
#define SCL2   (ATTN_SCALE * 1.4426950408889634f)

__global__ __launch_bounds__(256, 1) void flash_attn()
{
    extern __shared__ __align__(1024) char fsm[];
    const uint32_t sb = smem_u32(fsm);
    const int tid  = threadIdx.x;
    const int lane = tid & 31, wid = tid >> 5;
    const int gid = lane >> 2, tig = lane & 3;
    const int bz = blockIdx.y;
    const int q0 = blockIdx.x * 128 + wid * 16 + gid;

    const hf* Kh = g_kh  + (size_t)bz * NS * ND;
    const hf* Vh = g_vTh + (size_t)bz * ND * NS;

    uint32_t qh[8][4], ql[8][4];
    {
        const hf* Qh = g_qh + ((size_t)bz * NS + q0) * ND;
        const hf* Ql = g_ql + ((size_t)bz * NS + q0) * ND;
#pragma unroll
        for (int kc = 0; kc < 8; ++kc) {
            const int k0 = kc * 16 + tig * 2;
            qh[kc][0] = *(const uint32_t*)(Qh + k0);
            qh[kc][1] = *(const uint32_t*)(Qh + 8 * ND + k0);
            qh[kc][2] = *(const uint32_t*)(Qh + k0 + 8);
            qh[kc][3] = *(const uint32_t*)(Qh + 8 * ND + k0 + 8);
            ql[kc][0] = *(const uint32_t*)(Ql + k0);
            ql[kc][1] = *(const uint32_t*)(Ql + 8 * ND + k0);
            ql[kc][2] = *(const uint32_t*)(Ql + k0 + 8);
            ql[kc][3] = *(const uint32_t*)(Ql + 8 * ND + k0 + 8);
        }
    }

    auto issue = [&](int st, int kv0) {
        const uint32_t s = sb + (uint32_t)st * FSTAGE;
#pragma unroll
        for (int i = 0; i < 4; ++i) {
            const int idx = tid + i * 256;
            {   // K tile: 64 rows (s) x 128 d; pitch 272B
                const int r = idx >> 4, c = idx & 15;
                CP16(s + KH_OFF + (uint32_t)(r * 272 + c * 16),
                     Kh + (size_t)(kv0 + r) * ND + c * 8);
            }
            {   // V tile: 128 rows (d) x 64 s; pitch 144B
                const int r = idx >> 3, c = idx & 7;
                CP16(s + VH_OFF + (uint32_t)(r * 144 + c * 16),
                     Vh + (size_t)r * NS + kv0 + c * 8);
            }
        }
    };

    float oacc[16][4];
#pragma unroll
    for (int i = 0; i < 16; ++i)
#pragma unroll
        for (int q = 0; q < 4; ++q) oacc[i][q] = 0.0f;
    float m0 = -1e30f, m1 = -1e30f, l0 = 0.0f, l1 = 0.0f;

    issue(0, 0);   CP_COMMIT();
    issue(1, 64);  CP_COMMIT();

    int cs = 0, ws = 2;
    for (int t = 0; t < 16; ++t) {
        if (t + 1 < 16) CP_WAIT1(); else CP_WAIT0();
        __syncthreads();
        if (t + 2 < 16) { issue(ws, (t + 2) * 64); CP_COMMIT(); }

        const char* stg = fsm + (size_t)cs * FSTAGE;

        float sacc[8][4];
#pragma unroll
        for (int nf = 0; nf < 8; ++nf)
#pragma unroll
            for (int q = 0; q < 4; ++q) sacc[nf][q] = 0.0f;

#pragma unroll
        for (int kc = 0; kc < 8; ++kc)
#pragma unroll
            for (int nf = 0; nf < 8; ++nf) {
                const char* pb = stg + KH_OFF + (nf * 8 + gid) * 272 + kc * 32 + tig * 4;
                const uint32_t bh0 = *(const uint32_t*)(pb);
                const uint32_t bh1 = *(const uint32_t*)(pb + 16);
                mma16816(sacc[nf], qh[kc], bh0, bh1);
                mma16816(sacc[nf], ql[kc], bh0, bh1);
            }

        float rm0 = -1e30f, rm1 = -1e30f;
#pragma unroll
        for (int nf = 0; nf < 8; ++nf) {
            sacc[nf][0] *= SCL2; sacc[nf][1] *= SCL2;
            sacc[nf][2] *= SCL2; sacc[nf][3] *= SCL2;
            rm0 = fmaxf(rm0, fmaxf(sacc[nf][0], sacc[nf][1]));
            rm1 = fmaxf(rm1, fmaxf(sacc[nf][2], sacc[nf][3]));
        }
        rm0 = fmaxf(rm0, __shfl_xor_sync(0xffffffffu, rm0, 1));
        rm0 = fmaxf(rm0, __shfl_xor_sync(0xffffffffu, rm0, 2));
        rm1 = fmaxf(rm1, __shfl_xor_sync(0xffffffffu, rm1, 1));
        rm1 = fmaxf(rm1, __shfl_xor_sync(0xffffffffu, rm1, 2));

        const float mn0 = fmaxf(m0, rm0), mn1 = fmaxf(m1, rm1);
        const float al0 = exp2f(m0 - mn0), al1 = exp2f(m1 - mn1);
        m0 = mn0; m1 = mn1;

        float sum0 = 0.0f, sum1 = 0.0f;
#pragma unroll
        for (int nf = 0; nf < 8; ++nf) {
            sacc[nf][0] = exp2f(sacc[nf][0] - m0);
            sacc[nf][1] = exp2f(sacc[nf][1] - m0);
            sacc[nf][2] = exp2f(sacc[nf][2] - m1);
            sacc[nf][3] = exp2f(sacc[nf][3] - m1);
            sum0 += sacc[nf][0] + sacc[nf][1];
            sum1 += sacc[nf][2] + sacc[nf][3];
        }
        sum0 += __shfl_xor_sync(0xffffffffu, sum0, 1);
        sum0 += __shfl_xor_sync(0xffffffffu, sum0, 2);
        sum1 += __shfl_xor_sync(0xffffffffu, sum1, 1);
        sum1 += __shfl_xor_sync(0xffffffffu, sum1, 2);
        l0 = l0 * al0 + sum0;
        l1 = l1 * al1 + sum1;

#pragma unroll
        for (int nf = 0; nf < 16; ++nf) {
            oacc[nf][0] *= al0; oacc[nf][1] *= al0;
            oacc[nf][2] *= al1; oacc[nf][3] *= al1;
        }

#pragma unroll
        for (int kc = 0; kc < 4; ++kc) {
            uint32_t ph[4], pl[4];
            {
                hf a0, b0, a1, b1;
                split(sacc[2 * kc][0], a0, b0); split(sacc[2 * kc][1], a1, b1);
                ph[0] = pk(a0, a1); pl[0] = pk(b0, b1);
                split(sacc[2 * kc][2], a0, b0); split(sacc[2 * kc][3], a1, b1);
                ph[1] = pk(a0, a1); pl[1] = pk(b0, b1);
                split(sacc[2 * kc + 1][0], a0, b0); split(sacc[2 * kc + 1][1], a1, b1);
                ph[2] = pk(a0, a1); pl[2] = pk(b0, b1);
                split(sacc[2 * kc + 1][2], a0, b0); split(sacc[2 * kc + 1][3], a1, b1);
                ph[3] = pk(a0, a1); pl[3] = pk(b0, b1);
            }
#pragma unroll
            for (int nf = 0; nf < 16; ++nf) {
                const char* pb = stg + VH_OFF + (nf * 8 + gid) * 144 + kc * 32 + tig * 4;
                const uint32_t vb0 = *(const uint32_t*)(pb);
                const uint32_t vb1 = *(const uint32_t*)(pb + 16);
                mma16816(oacc[nf], ph, vb0, vb1);
                mma16816(oacc[nf], pl, vb0, vb1);
            }
        }

        if (++cs == 3) cs = 0;
        if (++ws == 3) ws = 0;
    }

    // ---- epilogue: normalize, split, store ctx hi/lo ----
    const float inv0 = 1.0f / l0, inv1 = 1.0f / l1;
    const int b = bz >> 4, h = bz & 15;
    const size_t base = ((size_t)(b * NS + q0)) * NE + h * ND;
#pragma unroll
    for (int nf = 0; nf < 16; ++nf) {
        const int d = nf * 8 + tig * 2;
        hf h0, lo0, h1, lo1;
        split(oacc[nf][0] * inv0, h0, lo0); split(oacc[nf][1] * inv0, h1, lo1);
        *(uint32_t*)(g_ch + base + d) = pk(h0, h1);
        *(uint32_t*)(g_cl + base + d) = pk(lo0, lo1);
        split(oacc[nf][2] * inv1, h0, lo0); split(oacc[nf][3] * inv1, h1, lo1);
        *(uint32_t*)(g_ch + base + 8 * NE + d) = pk(h0, h1);
        *(uint32_t*)(g_cl + base + 8 * NE + d) = pk(lo0, lo1);
    }
}

// ---------------- fp32 -> fp16 conversion -------------------------------------
__global__ __launch_bounds__(256) void cvt_k(const float4* __restrict__ src,
                                             int n4, int sel)
{
    const int i = blockIdx.x * 256 + threadIdx.x;
    if (i >= n4) return;
    const float4 v = src[i];

    if (sel == 0) {
        hf h0, l0, h1, l1, h2, l2, h3, l3;
        split(v.x, h0, l0); split(v.y, h1, l1);
        split(v.z, h2, l2); split(v.w, h3, l3);
        ((uint2*)g_xh)[i] = make_uint2(pk(h0, h1), pk(h2, h3));
        ((uint2*)g_xl)[i] = make_uint2(pk(l0, l1), pk(l2, l3));
    } else {
        hf* dst = sel == 1 ? g_wih : g_woh;
        ((uint2*)dst)[i] = make_uint2(
            pk(__float2half_rn(v.x), __float2half_rn(v.y)),
            pk(__float2half_rn(v.z), __float2half_rn(v.w)));
    }
}

// ---------------- host --------------------------------------------------------
extern "C" void kernel_launch(void* const* d_in, const int* in_sizes, int n_in,
                              void* d_out, int out_size)
{
    (void)in_sizes; (void)n_in; (void)out_size;
    const float* x  = (const float*)d_in[0];
    const float* wi = (const float*)d_in[1];
    const float* bi = (const float*)d_in[2];
    const float* wo = (const float*)d_in[3];
    const float* bo = (const float*)d_in[4];
    float* out = (float*)d_out;

    cudaFuncSetAttribute(gemm_mma<PQkv>, cudaFuncAttributeMaxDynamicSharedMemorySize, GSMEM);
    cudaFuncSetAttribute(gemm_mma<POut>, cudaFuncAttributeMaxDynamicSharedMemorySize, GSMEM);
    cudaFuncSetAttribute(flash_attn,     cudaFuncAttributeMaxDynamicSharedMemorySize, FSMEM);

    // 0) convert external fp32 operands to fp16 (x split, weights hi-only)
    cvt_k<<<(NB*NS*NE/4 + 255) / 256, 256>>>((const float4*)x,  NB*NS*NE/4, 0);
    cvt_k<<<(3*NE*NE/4  + 255) / 256, 256>>>((const float4*)wi, 3*NE*NE/4,  1);
    cvt_k<<<(NE*NE/4    + 255) / 256, 256>>>((const float4*)wo, NE*NE/4,    2);

    // 1) QKV projection (+bias, head scatter, V transposed)
    gemm_mma<PQkv><<<dim3(48, 32, 1), 256, GSMEM>>>(PQkv{bi}, NE);

    // 2-4) fused attention: scores + softmax + P·V
    flash_attn<<<dim3(NS / 128, NB * NH), 256, FSMEM>>>();

    // 5) out = ctx W_out^T + bias
    gemm_mma<POut><<<dim3(16, 32, 1), 256, GSMEM>>>(POut{bo, out}, NE);
}

// round 14
// speedup vs baseline: 1.5431x; 1.5431x over previous
#include <cuda_runtime.h>
#include <cuda_fp16.h>
#include <math.h>
#include <stdint.h>

#define NB 4
#define NS 1024
#define NE 2048
#define NH 16
#define ND 128
#define ATTN_SCALE 0.08838834764831845f

typedef __half hf;

// ---------------- scratch (device globals; referenced ONLY from device code) --
__device__ __align__(256) hf g_xh [(size_t)NB*NS*NE];
__device__ __align__(256) hf g_wih[(size_t)3*NE*NE];
__device__ __align__(256) hf g_woh[(size_t)NE*NE];
__device__ __align__(256) hf g_qh [(size_t)NB*NH*NS*ND];
__device__ __align__(256) hf g_ql [(size_t)NB*NH*NS*ND];
__device__ __align__(256) hf g_kh [(size_t)NB*NH*NS*ND];
__device__ __align__(256) hf g_vTh[(size_t)NB*NH*ND*NS];   // [b,h,d,s]
__device__ __align__(256) hf g_ch [(size_t)NB*NS*NE];

// ---------------- PTX helpers ------------------------------------------------
__device__ __forceinline__ uint32_t smem_u32(const void* p) {
    uint32_t a;
    asm("{ .reg .u64 t; cvta.to.shared.u64 t, %1; cvt.u32.u64 %0, t; }" : "=r"(a) : "l"(p));
    return a;
}

#define CP16(dst, src) \
    asm volatile("cp.async.cg.shared.global [%0], [%1], 16;" :: "r"(dst), "l"(src) : "memory")
#define CP_COMMIT() asm volatile("cp.async.commit_group;" ::: "memory")
#define CP_WAIT1()  asm volatile("cp.async.wait_group 1;" ::: "memory")
#define CP_WAIT0()  asm volatile("cp.async.wait_group 0;" ::: "memory")

__device__ __forceinline__ void ldsm4(uint32_t* r, uint32_t a) {
    asm volatile("ldmatrix.sync.aligned.m8n8.x4.shared.b16 {%0,%1,%2,%3}, [%4];"
                 : "=r"(r[0]), "=r"(r[1]), "=r"(r[2]), "=r"(r[3]) : "r"(a));
}
__device__ __forceinline__ void mma16816(float* d, const uint32_t* a, uint32_t b0, uint32_t b1) {
    asm volatile(
        "mma.sync.aligned.m16n8k16.row.col.f32.f16.f16.f32 "
        "{%0,%1,%2,%3}, {%4,%5,%6,%7}, {%8,%9}, {%0,%1,%2,%3};"
        : "+f"(d[0]), "+f"(d[1]), "+f"(d[2]), "+f"(d[3])
        : "r"(a[0]), "r"(a[1]), "r"(a[2]), "r"(a[3]), "r"(b0), "r"(b1));
}

__device__ __forceinline__ uint32_t pk(hf a, hf b) {
    return (uint32_t)__half_as_ushort(a) | ((uint32_t)__half_as_ushort(b) << 16);
}
__device__ __forceinline__ void split(float v, hf& h, hf& l) {
    h = __float2half_rn(v);
    l = __float2half_rn(v - __half2float(h));
}

// ---------------- operand-source / epilogue param structs -------------------
// ptr(w, bz): w=0 A (hi), w=1 B (hi). Single-pass fp16 projections.
struct PQkv {
    const float* bias;
    __device__ const hf* ptr(int w, int) const {
        return w == 0 ? g_xh : g_wih;
    }
    __device__ __forceinline__ void store2(int, int m, int n, float v0, float v1) const {
        v0 += bias[n]; v1 += bias[n + 1];
        const int which = n >> 11;
        const int e = n & 2047, h = e >> 7, d = e & 127;
        const int b = m >> 10, s = m & 1023;
        if (which == 0) {                       // Q: split (A of S-GEMM in flash)
            hf h0, l0, h1, l1;
            split(v0, h0, l0); split(v1, h1, l1);
            const size_t off = ((size_t)((b * NH + h) * NS + s)) * ND + d;
            *(uint32_t*)(g_qh + off) = pk(h0, h1);
            *(uint32_t*)(g_ql + off) = pk(l0, l1);
        } else if (which == 1) {                // K: hi only
            const size_t off = ((size_t)((b * NH + h) * NS + s)) * ND + d;
            *(uint32_t*)(g_kh + off) = pk(__float2half_rn(v0), __float2half_rn(v1));
        } else {                                // V: hi only, transposed [d][s]
            const size_t off = ((size_t)((b * NH + h) * ND + d)) * NS + s;
            g_vTh[off]      = __float2half_rn(v0);
            g_vTh[off + NS] = __float2half_rn(v1);
        }
    }
};

struct POut {
    const float* bias;
    float* out;
    __device__ const hf* ptr(int w, int) const {
        return w == 0 ? g_ch : g_woh;
    }
    __device__ __forceinline__ void store2(int, int m, int n, float v0, float v1) const {
        float2 o = make_float2(v0 + bias[n], v1 + bias[n + 1]);
        *(float2*)(out + (size_t)m * NE + n) = o;
    }
};

// ---------------- fp16 single-pass MMA GEMM (projections) ---------------------
// C[128,128] = A·B^T, fp32 accum. BK=32. 2 slots/stage (A, B) x 80B pitch
// = 20KB/stage; THREE stages (60KB, 2 CTAs/SM). R11-proven schedule:
// wait1 -> sync -> compute -> issue(c+2). (R12/R13 lessons: never drain the
// pipe; never issue the prefetch right after the barrier.)
#define SLOT2  10240u
#define STG2   20480u
#define GSMEM  (3 * 20480)

template <class P>
__global__ __launch_bounds__(256, 2) void gemm_mma(P p, int K)
{
    extern __shared__ __align__(1024) char gsm[];
    const uint32_t sb = smem_u32(gsm);
    const int tid  = threadIdx.x;
    const int lane = tid & 31, wid = tid >> 5;
    const int wm = wid >> 1, wn = wid & 1;       // 4x2 warp grid, warp tile 32x64
    const int gid = lane >> 2, tig = lane & 3;
    const int bz = blockIdx.z;
    const int m0 = blockIdx.y * 128, n0 = blockIdx.x * 128;

    const hf* a_p = p.ptr(0, bz);
    const hf* b_p = p.ptr(1, bz);

    auto issue = [&](int st, int kt) {
        const uint32_t s = sb + (uint32_t)st * STG2;
#pragma unroll
        for (int i = 0; i < 2; ++i) {
            const int idx = tid + i * 256;
            const int r = idx >> 2, c = idx & 3;
            const uint32_t d = (uint32_t)(r * 80 + c * 16);
            const size_t  o = (size_t)r * K + kt + c * 8;
            CP16(s + d,         a_p + (size_t)m0 * K + o);
            CP16(s + SLOT2 + d, b_p + (size_t)n0 * K + o);
        }
    };

    uint32_t a_off[2], b_off[4];
#pragma unroll
    for (int mi = 0; mi < 2; ++mi)
        a_off[mi] = (uint32_t)((wm * 32 + mi * 16 + (lane & 15)) * 80 + (lane >> 4) * 16);
#pragma unroll
    for (int nb = 0; nb < 4; ++nb) {
        const int rw = wn * 64 + nb * 16 + (lane & 7) + ((lane >> 4) & 1) * 8;
        b_off[nb] = (uint32_t)(rw * 80 + ((lane >> 3) & 1) * 16);
    }

    float acc[2][8][4];
#pragma unroll
    for (int i = 0; i < 2; ++i)
#pragma unroll
        for (int j = 0; j < 8; ++j)
#pragma unroll
            for (int q = 0; q < 4; ++q) acc[i][j][q] = 0.0f;

    issue(0, 0);      CP_COMMIT();
    issue(1, 32);     CP_COMMIT();

    const int NC = K >> 5;
    int cs = 0;       // c % 3
    int ws = 2;       // (c+2) % 3
    for (int c = 0; c < NC; ++c) {
        if (c + 1 < NC) CP_WAIT1(); else CP_WAIT0();
        __syncthreads();

        const uint32_t s = sb + (uint32_t)cs * STG2;
#pragma unroll
        for (int kh = 0; kh < 2; ++kh) {
            const uint32_t ka = kh * 32;

            uint32_t ah[2][4];
#pragma unroll
            for (int mi = 0; mi < 2; ++mi)
                ldsm4(ah[mi], s + a_off[mi] + ka);
#pragma unroll
            for (int nb = 0; nb < 4; ++nb) {
                uint32_t bh[4];
                ldsm4(bh, s + SLOT2 + b_off[nb] + ka);
#pragma unroll
                for (int mi = 0; mi < 2; ++mi) {
                    mma16816(acc[mi][nb * 2],     ah[mi], bh[0], bh[1]);
                    mma16816(acc[mi][nb * 2 + 1], ah[mi], bh[2], bh[3]);
                }
            }
        }

        if (c + 2 < NC) { issue(ws, (c + 2) << 5); CP_COMMIT(); }
        if (++cs == 3) cs = 0;
        if (++ws == 3) ws = 0;
    }

#pragma unroll
    for (int mi = 0; mi < 2; ++mi)
#pragma unroll
        for (int nf = 0; nf < 8; ++nf) {
            const int m = m0 + wm * 32 + mi * 16 + gid;
            const int n = n0 + wn * 64 + nf * 8 + tig * 2;
            p.store2(bz, m,     n, acc[mi][nf][0], acc[mi][nf][1]);
            p.store2(bz, m + 8, n, acc[mi][nf][2], acc[mi][nf][3]);
        }
}

// ---------------- fused flash attention (fp16, A-split, R11 schedule) ---------
// S = Qh·Kh + Ql·Kh ; O += Ph·Vh + Pl·Vh. ctx stored hi-only.
#define KH_OFF 0u
#define VH_OFF 17408u
#define FSTAGE 35840u
#define FSMEM  (3 * 35840)
#define SCL2   (ATTN_SCALE * 1.4426950408889634f)

__global__ __launch_bounds__(256, 1) void flash_attn()
{
    extern __shared__ __align__(1024) char fsm[];
    const uint32_t sb = smem_u32(fsm);
    const int tid  = threadIdx.x;
    const int lane = tid & 31, wid = tid >> 5;
    const int gid = lane >> 2, tig = lane & 3;
    const int bz = blockIdx.y;
    const int q0 = blockIdx.x * 128 + wid * 16 + gid;

    const hf* Kh = g_kh  + (size_t)bz * NS * ND;
    const hf* Vh = g_vTh + (size_t)bz * ND * NS;

    uint32_t qh[8][4], ql[8][4];
    {
        const hf* Qh = g_qh + ((size_t)bz * NS + q0) * ND;
        const hf* Ql = g_ql + ((size_t)bz * NS + q0) * ND;
#pragma unroll
        for (int kc = 0; kc < 8; ++kc) {
            const int k0 = kc * 16 + tig * 2;
            qh[kc][0] = *(const uint32_t*)(Qh + k0);
            qh[kc][1] = *(const uint32_t*)(Qh + 8 * ND + k0);
            qh[kc][2] = *(const uint32_t*)(Qh + k0 + 8);
            qh[kc][3] = *(const uint32_t*)(Qh + 8 * ND + k0 + 8);
            ql[kc][0] = *(const uint32_t*)(Ql + k0);
            ql[kc][1] = *(const uint32_t*)(Ql + 8 * ND + k0);
            ql[kc][2] = *(const uint32_t*)(Ql + k0 + 8);
            ql[kc][3] = *(const uint32_t*)(Ql + 8 * ND + k0 + 8);
        }
    }

    auto issue = [&](int st, int kv0) {
        const uint32_t s = sb + (uint32_t)st * FSTAGE;
#pragma unroll
        for (int i = 0; i < 4; ++i) {
            const int idx = tid + i * 256;
            {   // K tile: 64 rows (s) x 128 d; pitch 272B
                const int r = idx >> 4, c = idx & 15;
                CP16(s + KH_OFF + (uint32_t)(r * 272 + c * 16),
                     Kh + (size_t)(kv0 + r) * ND + c * 8);
            }
            {   // V tile: 128 rows (d) x 64 s; pitch 144B
                const int r = idx >> 3, c = idx & 7;
                CP16(s + VH_OFF + (uint32_t)(r * 144 + c * 16),
                     Vh + (size_t)r * NS + kv0 + c * 8);
            }
        }
    };

    float oacc[16][4];
#pragma unroll
    for (int i = 0; i < 16; ++i)
#pragma unroll
        for (int q = 0; q < 4; ++q) oacc[i][q] = 0.0f;
    float m0 = -1e30f, m1 = -1e30f, l0 = 0.0f, l1 = 0.0f;

    issue(0, 0);   CP_COMMIT();
    issue(1, 64);  CP_COMMIT();

    int cs = 0, ws = 2;
    for (int t = 0; t < 16; ++t) {
        if (t + 1 < 16) CP_WAIT1(); else CP_WAIT0();
        __syncthreads();

        const char* stg = fsm + (size_t)cs * FSTAGE;

        float sacc[8][4];
#pragma unroll
        for (int nf = 0; nf < 8; ++nf)
#pragma unroll
            for (int q = 0; q < 4; ++q) sacc[nf][q] = 0.0f;

#pragma unroll
        for (int kc = 0; kc < 8; ++kc)
#pragma unroll
            for (int nf = 0; nf < 8; ++nf) {
                const char* pb = stg + KH_OFF + (nf * 8 + gid) * 272 + kc * 32 + tig * 4;
                const uint32_t bh0 = *(const uint32_t*)(pb);
                const uint32_t bh1 = *(const uint32_t*)(pb + 16);
                mma16816(sacc[nf], qh[kc], bh0, bh1);
                mma16816(sacc[nf], ql[kc], bh0, bh1);
            }

        float rm0 = -1e30f, rm1 = -1e30f;
#pragma unroll
        for (int nf = 0; nf < 8; ++nf) {
            sacc[nf][0] *= SCL2; sacc[nf][1] *= SCL2;
            sacc[nf][2] *= SCL2; sacc[nf][3] *= SCL2;
            rm0 = fmaxf(rm0, fmaxf(sacc[nf][0], sacc[nf][1]));
            rm1 = fmaxf(rm1, fmaxf(sacc[nf][2], sacc[nf][3]));
        }
        rm0 = fmaxf(rm0, __shfl_xor_sync(0xffffffffu, rm0, 1));
        rm0 = fmaxf(rm0, __shfl_xor_sync(0xffffffffu, rm0, 2));
        rm1 = fmaxf(rm1, __shfl_xor_sync(0xffffffffu, rm1, 1));
        rm1 = fmaxf(rm1, __shfl_xor_sync(0xffffffffu, rm1, 2));

        const float mn0 = fmaxf(m0, rm0), mn1 = fmaxf(m1, rm1);
        const float al0 = exp2f(m0 - mn0), al1 = exp2f(m1 - mn1);
        m0 = mn0; m1 = mn1;

        float sum0 = 0.0f, sum1 = 0.0f;
#pragma unroll
        for (int nf = 0; nf < 8; ++nf) {
            sacc[nf][0] = exp2f(sacc[nf][0] - m0);
            sacc[nf][1] = exp2f(sacc[nf][1] - m0);
            sacc[nf][2] = exp2f(sacc[nf][2] - m1);
            sacc[nf][3] = exp2f(sacc[nf][3] - m1);
            sum0 += sacc[nf][0] + sacc[nf][1];
            sum1 += sacc[nf][2] + sacc[nf][3];
        }
        sum0 += __shfl_xor_sync(0xffffffffu, sum0, 1);
        sum0 += __shfl_xor_sync(0xffffffffu, sum0, 2);
        sum1 += __shfl_xor_sync(0xffffffffu, sum1, 1);
        sum1 += __shfl_xor_sync(0xffffffffu, sum1, 2);
        l0 = l0 * al0 + sum0;
        l1 = l1 * al1 + sum1;

#pragma unroll
        for (int nf = 0; nf < 16; ++nf) {
            oacc[nf][0] *= al0; oacc[nf][1] *= al0;
            oacc[nf][2] *= al1; oacc[nf][3] *= al1;
        }

#pragma unroll
        for (int kc = 0; kc < 4; ++kc) {
            uint32_t ph[4], pl[4];
            {
                hf a0, b0, a1, b1;
                split(sacc[2 * kc][0], a0, b0); split(sacc[2 * kc][1], a1, b1);
                ph[0] = pk(a0, a1); pl[0] = pk(b0, b1);
                split(sacc[2 * kc][2], a0, b0); split(sacc[2 * kc][3], a1, b1);
                ph[1] = pk(a0, a1); pl[1] = pk(b0, b1);
                split(sacc[2 * kc + 1][0], a0, b0); split(sacc[2 * kc + 1][1], a1, b1);
                ph[2] = pk(a0, a1); pl[2] = pk(b0, b1);
                split(sacc[2 * kc + 1][2], a0, b0); split(sacc[2 * kc + 1][3], a1, b1);
                ph[3] = pk(a0, a1); pl[3] = pk(b0, b1);
            }
#pragma unroll
            for (int nf = 0; nf < 16; ++nf) {
                const char* pb = stg + VH_OFF + (nf * 8 + gid) * 144 + kc * 32 + tig * 4;
                const uint32_t vb0 = *(const uint32_t*)(pb);
                const uint32_t vb1 = *(const uint32_t*)(pb + 16);
                mma16816(oacc[nf], ph, vb0, vb1);
                mma16816(oacc[nf], pl, vb0, vb1);
            }
        }

        if (t + 2 < 16) { issue(ws, (t + 2) * 64); CP_COMMIT(); }
        if (++cs == 3) cs = 0;
        if (++ws == 3) ws = 0;
    }

    // ---- epilogue: normalize, store ctx hi-only ----
    const float inv0 = 1.0f / l0, inv1 = 1.0f / l1;
    const int b = bz >> 4, h = bz & 15;
    const size_t base = ((size_t)(b * NS + q0)) * NE + h * ND;
#pragma unroll
    for (int nf = 0; nf < 16; ++nf) {
        const int d = nf * 8 + tig * 2;
        *(uint32_t*)(g_ch + base + d) =
            pk(__float2half_rn(oacc[nf][0] * inv0), __float2half_rn(oacc[nf][1] * inv0));
        *(uint32_t*)(g_ch + base + 8 * NE + d) =
            pk(__float2half_rn(oacc[nf][2] * inv1), __float2half_rn(oacc[nf][3] * inv1));
    }
}

// ---------------- fp32 -> fp16 conversion (hi only) ---------------------------
__global__ __launch_bounds__(256) void cvt_k(const float4* __restrict__ src,
                                             int n4, int sel)
{
    const int i = blockIdx.x * 256 + threadIdx.x;
    if (i >= n4) return;
    const float4 v = src[i];
    hf* dst = sel == 0 ? g_xh : sel == 1 ? g_wih : g_woh;
    ((uint2*)dst)[i] = make_uint2(
        pk(__float2half_rn(v.x), __float2half_rn(v.y)),
        pk(__float2half_rn(v.z), __float2half_rn(v.w)));
}

// ---------------- host --------------------------------------------------------
extern "C" void kernel_launch(void* const* d_in, const int* in_sizes, int n_in,
                              void* d_out, int out_size)
{
    (void)in_sizes; (void)n_in; (void)out_size;
    const float* x  = (const float*)d_in[0];
    const float* wi = (const float*)d_in[1];
    const float* bi = (const float*)d_in[2];
    const float* wo = (const float*)d_in[3];
    const float* bo = (const float*)d_in[4];
    float* out = (float*)d_out;

    cudaFuncSetAttribute(gemm_mma<PQkv>, cudaFuncAttributeMaxDynamicSharedMemorySize, GSMEM);
    cudaFuncSetAttribute(gemm_mma<POut>, cudaFuncAttributeMaxDynamicSharedMemorySize, GSMEM);
    cudaFuncSetAttribute(flash_attn,     cudaFuncAttributeMaxDynamicSharedMemorySize, FSMEM);

    // 0) convert external fp32 operands to fp16 (all hi-only)
    cvt_k<<<(NB*NS*NE/4 + 255) / 256, 256>>>((const float4*)x,  NB*NS*NE/4, 0);
    cvt_k<<<(3*NE*NE/4  + 255) / 256, 256>>>((const float4*)wi, 3*NE*NE/4,  1);
    cvt_k<<<(NE*NE/4    + 255) / 256, 256>>>((const float4*)wo, NE*NE/4,    2);

    // 1) QKV projection (+bias, head scatter, V transposed)
    gemm_mma<PQkv><<<dim3(48, 32, 1), 256, GSMEM>>>(PQkv{bi}, NE);

    // 2-4) fused attention: scores + softmax + P·V
    flash_attn<<<dim3(NS / 128, NB * NH), 256, FSMEM>>>();

    // 5) out = ctx W_out^T + bias
    gemm_mma<POut><<<dim3(16, 32, 1), 256, GSMEM>>>(POut{bo, out}, NE);
}

// round 15
// speedup vs baseline: 1.7683x; 1.1459x over previous
#include <cuda_runtime.h>
#include <cuda_fp16.h>
#include <math.h>
#include <stdint.h>

#define NB 4
#define NS 1024
#define NE 2048
#define NH 16
#define ND 128
#define ATTN_SCALE 0.08838834764831845f

typedef __half hf;

// ---------------- scratch (device globals; referenced ONLY from device code) --
__device__ __align__(256) hf g_xh [(size_t)NB*NS*NE];
__device__ __align__(256) hf g_wih[(size_t)3*NE*NE];
__device__ __align__(256) hf g_woh[(size_t)NE*NE];
__device__ __align__(256) hf g_qh [(size_t)NB*NH*NS*ND];
__device__ __align__(256) hf g_ql [(size_t)NB*NH*NS*ND];
__device__ __align__(256) hf g_kh [(size_t)NB*NH*NS*ND];
__device__ __align__(256) hf g_vTh[(size_t)NB*NH*ND*NS];   // [b,h,d,s]
__device__ __align__(256) hf g_ch [(size_t)NB*NS*NE];

// ---------------- PTX helpers ------------------------------------------------
__device__ __forceinline__ uint32_t smem_u32(const void* p) {
    uint32_t a;
    asm("{ .reg .u64 t; cvta.to.shared.u64 t, %1; cvt.u32.u64 %0, t; }" : "=r"(a) : "l"(p));
    return a;
}

#define CP16(dst, src) \
    asm volatile("cp.async.cg.shared.global [%0], [%1], 16;" :: "r"(dst), "l"(src) : "memory")
#define CP_COMMIT() asm volatile("cp.async.commit_group;" ::: "memory")
#define CP_WAIT1()  asm volatile("cp.async.wait_group 1;" ::: "memory")
#define CP_WAIT0()  asm volatile("cp.async.wait_group 0;" ::: "memory")

__device__ __forceinline__ void ldsm4(uint32_t* r, uint32_t a) {
    asm volatile("ldmatrix.sync.aligned.m8n8.x4.shared.b16 {%0,%1,%2,%3}, [%4];"
                 : "=r"(r[0]), "=r"(r[1]), "=r"(r[2]), "=r"(r[3]) : "r"(a));
}
__device__ __forceinline__ void mma16816(float* d, const uint32_t* a, uint32_t b0, uint32_t b1) {
    asm volatile(
        "mma.sync.aligned.m16n8k16.row.col.f32.f16.f16.f32 "
        "{%0,%1,%2,%3}, {%4,%5,%6,%7}, {%8,%9}, {%0,%1,%2,%3};"
        : "+f"(d[0]), "+f"(d[1]), "+f"(d[2]), "+f"(d[3])
        : "r"(a[0]), "r"(a[1]), "r"(a[2]), "r"(a[3]), "r"(b0), "r"(b1));
}

__device__ __forceinline__ uint32_t pk(hf a, hf b) {
    return (uint32_t)__half_as_ushort(a) | ((uint32_t)__half_as_ushort(b) << 16);
}
__device__ __forceinline__ void split(float v, hf& h, hf& l) {
    h = __float2half_rn(v);
    l = __float2half_rn(v - __half2float(h));
}

// ---------------- operand-source / epilogue param structs -------------------
struct PQkv {
    const float* bias;
    __device__ const hf* ptr(int w, int) const {
        return w == 0 ? g_xh : g_wih;
    }
    __device__ __forceinline__ void store2(int, int m, int n, float v0, float v1) const {
        v0 += bias[n]; v1 += bias[n + 1];
        const int which = n >> 11;
        const int e = n & 2047, h = e >> 7, d = e & 127;
        const int b = m >> 10, s = m & 1023;
        if (which == 0) {                       // Q: split (A of S-GEMM in flash)
            hf h0, l0, h1, l1;
            split(v0, h0, l0); split(v1, h1, l1);
            const size_t off = ((size_t)((b * NH + h) * NS + s)) * ND + d;
            *(uint32_t*)(g_qh + off) = pk(h0, h1);
            *(uint32_t*)(g_ql + off) = pk(l0, l1);
        } else if (which == 1) {                // K: hi only
            const size_t off = ((size_t)((b * NH + h) * NS + s)) * ND + d;
            *(uint32_t*)(g_kh + off) = pk(__float2half_rn(v0), __float2half_rn(v1));
        } else {                                // V: hi only, transposed [d][s]
            const size_t off = ((size_t)((b * NH + h) * ND + d)) * NS + s;
            g_vTh[off]      = __float2half_rn(v0);
            g_vTh[off + NS] = __float2half_rn(v1);
        }
    }
};

struct POut {
    const float* bias;
    float* out;
    __device__ const hf* ptr(int w, int) const {
        return w == 0 ? g_ch : g_woh;
    }
    __device__ __forceinline__ void store2(int, int m, int n, float v0, float v1) const {
        float2 o = make_float2(v0 + bias[n], v1 + bias[n + 1]);
        *(float2*)(out + (size_t)m * NE + n) = o;
    }
};

// ---------------- fp16 single-pass MMA GEMM (projections) ---------------------
// C[128,128] = A·B^T, fp32 accum. BK=64.
// 2 slots/stage (A, B): 128 rows x 144B pitch (128B data + 16 pad) = 18KB/slot,
// 36KB/stage; THREE stages (108KB dynamic; 2 CTAs/SM = 216KB <= 228KB).
// Proven schedule: wait1 -> sync -> compute -> issue(c+2). Barriers: 32/CTA
// (vs 64 at BK=32) with the pipe never draining. (R12 failed BK=64 only
// because of 2-stage drain + top-issue; both rules respected here.)
#define SLOT2  18432u
#define STG2   36864u
#define GSMEM  (3 * 36864)

template <class P>
__global__ __launch_bounds__(256, 2) void gemm_mma(P p, int K)
{
    extern __shared__ __align__(1024) char gsm[];
    const uint32_t sb = smem_u32(gsm);
    const int tid  = threadIdx.x;
    const int lane = tid & 31, wid = tid >> 5;
    const int wm = wid >> 1, wn = wid & 1;       // 4x2 warp grid, warp tile 32x64
    const int gid = lane >> 2, tig = lane & 3;
    const int bz = blockIdx.z;
    const int m0 = blockIdx.y * 128, n0 = blockIdx.x * 128;

    const hf* a_p = p.ptr(0, bz);
    const hf* b_p = p.ptr(1, bz);

    auto issue = [&](int st, int kt) {
        const uint32_t s = sb + (uint32_t)st * STG2;
#pragma unroll
        for (int i = 0; i < 4; ++i) {
            const int idx = tid + i * 256;
            const int r = idx >> 3, c = idx & 7;
            const uint32_t d = (uint32_t)(r * 144 + c * 16);
            const size_t  o = (size_t)r * K + kt + c * 8;
            CP16(s + d,         a_p + (size_t)m0 * K + o);
            CP16(s + SLOT2 + d, b_p + (size_t)n0 * K + o);
        }
    };

    uint32_t a_off[2], b_off[4];
#pragma unroll
    for (int mi = 0; mi < 2; ++mi)
        a_off[mi] = (uint32_t)((wm * 32 + mi * 16 + (lane & 15)) * 144 + (lane >> 4) * 16);
#pragma unroll
    for (int nb = 0; nb < 4; ++nb) {
        const int rw = wn * 64 + nb * 16 + (lane & 7) + ((lane >> 4) & 1) * 8;
        b_off[nb] = (uint32_t)(rw * 144 + ((lane >> 3) & 1) * 16);
    }

    float acc[2][8][4];
#pragma unroll
    for (int i = 0; i < 2; ++i)
#pragma unroll
        for (int j = 0; j < 8; ++j)
#pragma unroll
            for (int q = 0; q < 4; ++q) acc[i][j][q] = 0.0f;

    issue(0, 0);      CP_COMMIT();
    issue(1, 64);     CP_COMMIT();

    const int NC = K >> 6;
    int cs = 0;       // c % 3
    int ws = 2;       // (c+2) % 3
    for (int c = 0; c < NC; ++c) {
        if (c + 1 < NC) CP_WAIT1(); else CP_WAIT0();
        __syncthreads();

        const uint32_t s = sb + (uint32_t)cs * STG2;
#pragma unroll
        for (int kh = 0; kh < 4; ++kh) {
            const uint32_t ka = kh * 32;     // 16 k-elems = 32 bytes

            uint32_t ah[2][4];
#pragma unroll
            for (int mi = 0; mi < 2; ++mi)
                ldsm4(ah[mi], s + a_off[mi] + ka);
#pragma unroll
            for (int nb = 0; nb < 4; ++nb) {
                uint32_t bh[4];
                ldsm4(bh, s + SLOT2 + b_off[nb] + ka);
#pragma unroll
                for (int mi = 0; mi < 2; ++mi) {
                    mma16816(acc[mi][nb * 2],     ah[mi], bh[0], bh[1]);
                    mma16816(acc[mi][nb * 2 + 1], ah[mi], bh[2], bh[3]);
                }
            }
        }

        if (c + 2 < NC) { issue(ws, (c + 2) << 6); CP_COMMIT(); }
        if (++cs == 3) cs = 0;
        if (++ws == 3) ws = 0;
    }

#pragma unroll
    for (int mi = 0; mi < 2; ++mi)
#pragma unroll
        for (int nf = 0; nf < 8; ++nf) {
            const int m = m0 + wm * 32 + mi * 16 + gid;
            const int n = n0 + wn * 64 + nf * 8 + tig * 2;
            p.store2(bz, m,     n, acc[mi][nf][0], acc[mi][nf][1]);
            p.store2(bz, m + 8, n, acc[mi][nf][2], acc[mi][nf][3]);
        }
}

// ---------------- fused flash attention (fp16; Q split, P hi-only) ------------
// S = Qh·Kh + Ql·Kh ; O += Ph·Vh. ctx stored hi-only.
#define KH_OFF 0u
#define VH_OFF 17408u
#define FSTAGE 35840u
#define FSMEM  (3 * 35840)
#define SCL2   (ATTN_SCALE * 1.4426950408889634f)

__global__ __launch_bounds__(256, 1) void flash_attn()
{
    extern __shared__ __align__(1024) char fsm[];
    const uint32_t sb = smem_u32(fsm);
    const int tid  = threadIdx.x;
    const int lane = tid & 31, wid = tid >> 5;
    const int gid = lane >> 2, tig = lane & 3;
    const int bz = blockIdx.y;
    const int q0 = blockIdx.x * 128 + wid * 16 + gid;

    const hf* Kh = g_kh  + (size_t)bz * NS * ND;
    const hf* Vh = g_vTh + (size_t)bz * ND * NS;

    uint32_t qh[8][4], ql[8][4];
    {
        const hf* Qh = g_qh + ((size_t)bz * NS + q0) * ND;
        const hf* Ql = g_ql + ((size_t)bz * NS + q0) * ND;
#pragma unroll
        for (int kc = 0; kc < 8; ++kc) {
            const int k0 = kc * 16 + tig * 2;
            qh[kc][0] = *(const uint32_t*)(Qh + k0);
            qh[kc][1] = *(const uint32_t*)(Qh + 8 * ND + k0);
            qh[kc][2] = *(const uint32_t*)(Qh + k0 + 8);
            qh[kc][3] = *(const uint32_t*)(Qh + 8 * ND + k0 + 8);
            ql[kc][0] = *(const uint32_t*)(Ql + k0);
            ql[kc][1] = *(const uint32_t*)(Ql + 8 * ND + k0);
            ql[kc][2] = *(const uint32_t*)(Ql + k0 + 8);
            ql[kc][3] = *(const uint32_t*)(Ql + 8 * ND + k0 + 8);
        }
    }

    auto issue = [&](int st, int kv0) {
        const uint32_t s = sb + (uint32_t)st * FSTAGE;
#pragma unroll
        for (int i = 0; i < 4; ++i) {
            const int idx = tid + i * 256;
            {   // K tile: 64 rows (s) x 128 d; pitch 272B
                const int r = idx >> 4, c = idx & 15;
                CP16(s + KH_OFF + (uint32_t)(r * 272 + c * 16),
                     Kh + (size_t)(kv0 + r) * ND + c * 8);
            }
            {   // V tile: 128 rows (d) x 64 s; pitch 144B
                const int r = idx >> 3, c = idx & 7;
                CP16(s + VH_OFF + (uint32_t)(r * 144 + c * 16),
                     Vh + (size_t)r * NS + kv0 + c * 8);
            }
        }
    };

    float oacc[16][4];
#pragma unroll
    for (int i = 0; i < 16; ++i)
#pragma unroll
        for (int q = 0; q < 4; ++q) oacc[i][q] = 0.0f;
    float m0 = -1e30f, m1 = -1e30f, l0 = 0.0f, l1 = 0.0f;

    issue(0, 0);   CP_COMMIT();
    issue(1, 64);  CP_COMMIT();

    int cs = 0, ws = 2;
    for (int t = 0; t < 16; ++t) {
        if (t + 1 < 16) CP_WAIT1(); else CP_WAIT0();
        __syncthreads();

        const char* stg = fsm + (size_t)cs * FSTAGE;

        float sacc[8][4];
#pragma unroll
        for (int nf = 0; nf < 8; ++nf)
#pragma unroll
            for (int q = 0; q < 4; ++q) sacc[nf][q] = 0.0f;

#pragma unroll
        for (int kc = 0; kc < 8; ++kc)
#pragma unroll
            for (int nf = 0; nf < 8; ++nf) {
                const char* pb = stg + KH_OFF + (nf * 8 + gid) * 272 + kc * 32 + tig * 4;
                const uint32_t bh0 = *(const uint32_t*)(pb);
                const uint32_t bh1 = *(const uint32_t*)(pb + 16);
                mma16816(sacc[nf], qh[kc], bh0, bh1);
                mma16816(sacc[nf], ql[kc], bh0, bh1);
            }

        float rm0 = -1e30f, rm1 = -1e30f;
#pragma unroll
        for (int nf = 0; nf < 8; ++nf) {
            sacc[nf][0] *= SCL2; sacc[nf][1] *= SCL2;
            sacc[nf][2] *= SCL2; sacc[nf][3] *= SCL2;
            rm0 = fmaxf(rm0, fmaxf(sacc[nf][0], sacc[nf][1]));
            rm1 = fmaxf(rm1, fmaxf(sacc[nf][2], sacc[nf][3]));
        }
        rm0 = fmaxf(rm0, __shfl_xor_sync(0xffffffffu, rm0, 1));
        rm0 = fmaxf(rm0, __shfl_xor_sync(0xffffffffu, rm0, 2));
        rm1 = fmaxf(rm1, __shfl_xor_sync(0xffffffffu, rm1, 1));
        rm1 = fmaxf(rm1, __shfl_xor_sync(0xffffffffu, rm1, 2));

        const float mn0 = fmaxf(m0, rm0), mn1 = fmaxf(m1, rm1);
        const float al0 = exp2f(m0 - mn0), al1 = exp2f(m1 - mn1);
        m0 = mn0; m1 = mn1;

        float sum0 = 0.0f, sum1 = 0.0f;
#pragma unroll
        for (int nf = 0; nf < 8; ++nf) {
            sacc[nf][0] = exp2f(sacc[nf][0] - m0);
            sacc[nf][1] = exp2f(sacc[nf][1] - m0);
            sacc[nf][2] = exp2f(sacc[nf][2] - m1);
            sacc[nf][3] = exp2f(sacc[nf][3] - m1);
            sum0 += sacc[nf][0] + sacc[nf][1];
            sum1 += sacc[nf][2] + sacc[nf][3];
        }
        sum0 += __shfl_xor_sync(0xffffffffu, sum0, 1);
        sum0 += __shfl_xor_sync(0xffffffffu, sum0, 2);
        sum1 += __shfl_xor_sync(0xffffffffu, sum1, 1);
        sum1 += __shfl_xor_sync(0xffffffffu, sum1, 2);
        l0 = l0 * al0 + sum0;
        l1 = l1 * al1 + sum1;

#pragma unroll
        for (int nf = 0; nf < 16; ++nf) {
            oacc[nf][0] *= al0; oacc[nf][1] *= al0;
            oacc[nf][2] *= al1; oacc[nf][3] *= al1;
        }

#pragma unroll
        for (int kc = 0; kc < 4; ++kc) {
            uint32_t ph[4];
            ph[0] = pk(__float2half_rn(sacc[2 * kc][0]),     __float2half_rn(sacc[2 * kc][1]));
            ph[1] = pk(__float2half_rn(sacc[2 * kc][2]),     __float2half_rn(sacc[2 * kc][3]));
            ph[2] = pk(__float2half_rn(sacc[2 * kc + 1][0]), __float2half_rn(sacc[2 * kc + 1][1]));
            ph[3] = pk(__float2half_rn(sacc[2 * kc + 1][2]), __float2half_rn(sacc[2 * kc + 1][3]));
#pragma unroll
            for (int nf = 0; nf < 16; ++nf) {
                const char* pb = stg + VH_OFF + (nf * 8 + gid) * 144 + kc * 32 + tig * 4;
                const uint32_t vb0 = *(const uint32_t*)(pb);
                const uint32_t vb1 = *(const uint32_t*)(pb + 16);
                mma16816(oacc[nf], ph, vb0, vb1);
            }
        }

        if (t + 2 < 16) { issue(ws, (t + 2) * 64); CP_COMMIT(); }
        if (++cs == 3) cs = 0;
        if (++ws == 3) ws = 0;
    }

    // ---- epilogue: normalize, store ctx hi-only ----
    const float inv0 = 1.0f / l0, inv1 = 1.0f / l1;
    const int b = bz >> 4, h = bz & 15;
    const size_t base = ((size_t)(b * NS + q0)) * NE + h * ND;
#pragma unroll
    for (int nf = 0; nf < 16; ++nf) {
        const int d = nf * 8 + tig * 2;
        *(uint32_t*)(g_ch + base + d) =
            pk(__float2half_rn(oacc[nf][0] * inv0), __float2half_rn(oacc[nf][1] * inv0));
        *(uint32_t*)(g_ch + base + 8 * NE + d) =
            pk(__float2half_rn(oacc[nf][2] * inv1), __float2half_rn(oacc[nf][3] * inv1));
    }
}

// ---------------- fp32 -> fp16 conversion (hi only) ---------------------------
__global__ __launch_bounds__(256) void cvt_k(const float4* __restrict__ src,
                                             int n4, int sel)
{
    const int i = blockIdx.x * 256 + threadIdx.x;
    if (i >= n4) return;
    const float4 v = src[i];
    hf* dst = sel == 0 ? g_xh : sel == 1 ? g_wih : g_woh;
    ((uint2*)dst)[i] = make_uint2(
        pk(__float2half_rn(v.x), __float2half_rn(v.y)),
        pk(__float2half_rn(v.z), __float2half_rn(v.w)));
}

// ---------------- host --------------------------------------------------------
extern "C" void kernel_launch(void* const* d_in, const int* in_sizes, int n_in,
                              void* d_out, int out_size)
{
    (void)in_sizes; (void)n_in; (void)out_size;
    const float* x  = (const float*)d_in[0];
    const float* wi = (const float*)d_in[1];
    const float* bi = (const float*)d_in[2];
    const float* wo = (const float*)d_in[3];
    const float* bo = (const float*)d_in[4];
    float* out = (float*)d_out;

    cudaFuncSetAttribute(gemm_mma<PQkv>, cudaFuncAttributeMaxDynamicSharedMemorySize, GSMEM);
    cudaFuncSetAttribute(gemm_mma<POut>, cudaFuncAttributeMaxDynamicSharedMemorySize, GSMEM);
    cudaFuncSetAttribute(flash_attn,     cudaFuncAttributeMaxDynamicSharedMemorySize, FSMEM);

    // 0) convert external fp32 operands to fp16 (all hi-only)
    cvt_k<<<(NB*NS*NE/4 + 255) / 256, 256>>>((const float4*)x,  NB*NS*NE/4, 0);
    cvt_k<<<(3*NE*NE/4  + 255) / 256, 256>>>((const float4*)wi, 3*NE*NE/4,  1);
    cvt_k<<<(NE*NE/4    + 255) / 256, 256>>>((const float4*)wo, NE*NE/4,    2);

    // 1) QKV projection (+bias, head scatter, V transposed)
    gemm_mma<PQkv><<<dim3(48, 32, 1), 256, GSMEM>>>(PQkv{bi}, NE);

    // 2-4) fused attention: scores + softmax + P·V
    flash_attn<<<dim3(NS / 128, NB * NH), 256, FSMEM>>>();

    // 5) out = ctx W_out^T + bias
    gemm_mma<POut><<<dim3(16, 32, 1), 256, GSMEM>>>(POut{bo, out}, NE);
}

// round 16
// speedup vs baseline: 1.7887x; 1.0115x over previous
#include <cuda_runtime.h>
#include <cuda_fp16.h>
#include <math.h>
#include <stdint.h>

#define NB 4
#define NS 1024
#define NE 2048
#define NH 16
#define ND 128
#define ATTN_SCALE 0.08838834764831845f

typedef __half hf;

// ---------------- scratch (device globals; referenced ONLY from device code) --
__device__ __align__(256) hf g_xh [(size_t)NB*NS*NE];
__device__ __align__(256) hf g_wih[(size_t)3*NE*NE];
__device__ __align__(256) hf g_woh[(size_t)NE*NE];
__device__ __align__(256) hf g_qh [(size_t)NB*NH*NS*ND];
__device__ __align__(256) hf g_ql [(size_t)NB*NH*NS*ND];
__device__ __align__(256) hf g_kh [(size_t)NB*NH*NS*ND];
__device__ __align__(256) hf g_vTh[(size_t)NB*NH*ND*NS];   // [b,h,d,s]
__device__ __align__(256) hf g_ch [(size_t)NB*NS*NE];

// ---------------- PTX helpers ------------------------------------------------
__device__ __forceinline__ uint32_t smem_u32(const void* p) {
    uint32_t a;
    asm("{ .reg .u64 t; cvta.to.shared.u64 t, %1; cvt.u32.u64 %0, t; }" : "=r"(a) : "l"(p));
    return a;
}

#define CP16(dst, src) \
    asm volatile("cp.async.cg.shared.global [%0], [%1], 16;" :: "r"(dst), "l"(src) : "memory")
#define CP_COMMIT() asm volatile("cp.async.commit_group;" ::: "memory")
#define CP_WAIT1()  asm volatile("cp.async.wait_group 1;" ::: "memory")
#define CP_WAIT0()  asm volatile("cp.async.wait_group 0;" ::: "memory")

__device__ __forceinline__ void ldsm4(uint32_t* r, uint32_t a) {
    asm volatile("ldmatrix.sync.aligned.m8n8.x4.shared.b16 {%0,%1,%2,%3}, [%4];"
                 : "=r"(r[0]), "=r"(r[1]), "=r"(r[2]), "=r"(r[3]) : "r"(a));
}
__device__ __forceinline__ void mma16816(float* d, const uint32_t* a, uint32_t b0, uint32_t b1) {
    asm volatile(
        "mma.sync.aligned.m16n8k16.row.col.f32.f16.f16.f32 "
        "{%0,%1,%2,%3}, {%4,%5,%6,%7}, {%8,%9}, {%0,%1,%2,%3};"
        : "+f"(d[0]), "+f"(d[1]), "+f"(d[2]), "+f"(d[3])
        : "r"(a[0]), "r"(a[1]), "r"(a[2]), "r"(a[3]), "r"(b0), "r"(b1));
}

__device__ __forceinline__ uint32_t pk(hf a, hf b) {
    return (uint32_t)__half_as_ushort(a) | ((uint32_t)__half_as_ushort(b) << 16);
}
__device__ __forceinline__ void split(float v, hf& h, hf& l) {
    h = __float2half_rn(v);
    l = __float2half_rn(v - __half2float(h));
}

// ---------------- operand-source / epilogue param structs -------------------
struct PQkv {
    const float* bias;
    __device__ const hf* ptr(int w, int) const {
        return w == 0 ? g_xh : g_wih;
    }
    __device__ __forceinline__ void store2(int, int m, int n, float v0, float v1) const {
        v0 += bias[n]; v1 += bias[n + 1];
        const int which = n >> 11;
        const int e = n & 2047, h = e >> 7, d = e & 127;
        const int b = m >> 10, s = m & 1023;
        if (which == 0) {                       // Q: split (A of S-GEMM in flash)
            hf h0, l0, h1, l1;
            split(v0, h0, l0); split(v1, h1, l1);
            const size_t off = ((size_t)((b * NH + h) * NS + s)) * ND + d;
            *(uint32_t*)(g_qh + off) = pk(h0, h1);
            *(uint32_t*)(g_ql + off) = pk(l0, l1);
        } else if (which == 1) {                // K: hi only
            const size_t off = ((size_t)((b * NH + h) * NS + s)) * ND + d;
            *(uint32_t*)(g_kh + off) = pk(__float2half_rn(v0), __float2half_rn(v1));
        } else {                                // V: hi only, transposed [d][s]
            const size_t off = ((size_t)((b * NH + h) * ND + d)) * NS + s;
            g_vTh[off]      = __float2half_rn(v0);
            g_vTh[off + NS] = __float2half_rn(v1);
        }
    }
};

struct POut {
    const float* bias;
    float* out;
    __device__ const hf* ptr(int w, int) const {
        return w == 0 ? g_ch : g_woh;
    }
    __device__ __forceinline__ void store2(int, int m, int n, float v0, float v1) const {
        float2 o = make_float2(v0 + bias[n], v1 + bias[n + 1]);
        *(float2*)(out + (size_t)m * NE + n) = o;
    }
};

// ---------------- fp16 single-pass MMA GEMM (projections) ---------------------
// C[128,128] = A·B^T, fp32 accum. BK=64. (unchanged from R15 — best config)
#define SLOT2  18432u
#define STG2   36864u
#define GSMEM  (3 * 36864)

template <class P>
__global__ __launch_bounds__(256, 2) void gemm_mma(P p, int K)
{
    extern __shared__ __align__(1024) char gsm[];
    const uint32_t sb = smem_u32(gsm);
    const int tid  = threadIdx.x;
    const int lane = tid & 31, wid = tid >> 5;
    const int wm = wid >> 1, wn = wid & 1;
    const int gid = lane >> 2, tig = lane & 3;
    const int bz = blockIdx.z;
    const int m0 = blockIdx.y * 128, n0 = blockIdx.x * 128;

    const hf* a_p = p.ptr(0, bz);
    const hf* b_p = p.ptr(1, bz);

    auto issue = [&](int st, int kt) {
        const uint32_t s = sb + (uint32_t)st * STG2;
#pragma unroll
        for (int i = 0; i < 4; ++i) {
            const int idx = tid + i * 256;
            const int r = idx >> 3, c = idx & 7;
            const uint32_t d = (uint32_t)(r * 144 + c * 16);
            const size_t  o = (size_t)r * K + kt + c * 8;
            CP16(s + d,         a_p + (size_t)m0 * K + o);
            CP16(s + SLOT2 + d, b_p + (size_t)n0 * K + o);
        }
    };

    uint32_t a_off[2], b_off[4];
#pragma unroll
    for (int mi = 0; mi < 2; ++mi)
        a_off[mi] = (uint32_t)((wm * 32 + mi * 16 + (lane & 15)) * 144 + (lane >> 4) * 16);
#pragma unroll
    for (int nb = 0; nb < 4; ++nb) {
        const int rw = wn * 64 + nb * 16 + (lane & 7) + ((lane >> 4) & 1) * 8;
        b_off[nb] = (uint32_t)(rw * 144 + ((lane >> 3) & 1) * 16);
    }

    float acc[2][8][4];
#pragma unroll
    for (int i = 0; i < 2; ++i)
#pragma unroll
        for (int j = 0; j < 8; ++j)
#pragma unroll
            for (int q = 0; q < 4; ++q) acc[i][j][q] = 0.0f;

    issue(0, 0);      CP_COMMIT();
    issue(1, 64);     CP_COMMIT();

    const int NC = K >> 6;
    int cs = 0, ws = 2;
    for (int c = 0; c < NC; ++c) {
        if (c + 1 < NC) CP_WAIT1(); else CP_WAIT0();
        __syncthreads();

        const uint32_t s = sb + (uint32_t)cs * STG2;
#pragma unroll
        for (int kh = 0; kh < 4; ++kh) {
            const uint32_t ka = kh * 32;

            uint32_t ah[2][4];
#pragma unroll
            for (int mi = 0; mi < 2; ++mi)
                ldsm4(ah[mi], s + a_off[mi] + ka);
#pragma unroll
            for (int nb = 0; nb < 4; ++nb) {
                uint32_t bh[4];
                ldsm4(bh, s + SLOT2 + b_off[nb] + ka);
#pragma unroll
                for (int mi = 0; mi < 2; ++mi) {
                    mma16816(acc[mi][nb * 2],     ah[mi], bh[0], bh[1]);
                    mma16816(acc[mi][nb * 2 + 1], ah[mi], bh[2], bh[3]);
                }
            }
        }

        if (c + 2 < NC) { issue(ws, (c + 2) << 6); CP_COMMIT(); }
        if (++cs == 3) cs = 0;
        if (++ws == 3) ws = 0;
    }

#pragma unroll
    for (int mi = 0; mi < 2; ++mi)
#pragma unroll
        for (int nf = 0; nf < 8; ++nf) {
            const int m = m0 + wm * 32 + mi * 16 + gid;
            const int n = n0 + wn * 64 + nf * 8 + tig * 2;
            p.store2(bz, m,     n, acc[mi][nf][0], acc[mi][nf][1]);
            p.store2(bz, m + 8, n, acc[mi][nf][2], acc[mi][nf][3]);
        }
}

// ---------------- fused flash attention (fp16; Q split, P hi-only) ------------
// S = Qh·Kh + Ql·Kh ; O += Ph·Vh. K/V fragments via ldmatrix.x4 (4x fewer
// shared-load instructions than scalar LDS; fragments bit-identical, so
// rel_err must not change).
#define KH_OFF 0u
#define VH_OFF 17408u
#define FSTAGE 35840u
#define FSMEM  (3 * 35840)
#define SCL2   (ATTN_SCALE * 1.4426950408889634f)

__global__ __launch_bounds__(256, 1) void flash_attn()
{
    extern __shared__ __align__(1024) char fsm[];
    const uint32_t sb = smem_u32(fsm);
    const int tid  = threadIdx.x;
    const int lane = tid & 31, wid = tid >> 5;
    const int gid = lane >> 2, tig = lane & 3;
    const int bz = blockIdx.y;
    const int q0 = blockIdx.x * 128 + wid * 16 + gid;

    const hf* Kh = g_kh  + (size_t)bz * NS * ND;
    const hf* Vh = g_vTh + (size_t)bz * ND * NS;

    uint32_t qh[8][4], ql[8][4];
    {
        const hf* Qh = g_qh + ((size_t)bz * NS + q0) * ND;
        const hf* Ql = g_ql + ((size_t)bz * NS + q0) * ND;
#pragma unroll
        for (int kc = 0; kc < 8; ++kc) {
            const int k0 = kc * 16 + tig * 2;
            qh[kc][0] = *(const uint32_t*)(Qh + k0);
            qh[kc][1] = *(const uint32_t*)(Qh + 8 * ND + k0);
            qh[kc][2] = *(const uint32_t*)(Qh + k0 + 8);
            qh[kc][3] = *(const uint32_t*)(Qh + 8 * ND + k0 + 8);
            ql[kc][0] = *(const uint32_t*)(Ql + k0);
            ql[kc][1] = *(const uint32_t*)(Ql + 8 * ND + k0);
            ql[kc][2] = *(const uint32_t*)(Ql + k0 + 8);
            ql[kc][3] = *(const uint32_t*)(Ql + 8 * ND + k0 + 8);
        }
    }

    // ldmatrix fragment offsets (same derivation as gemm_mma's proven b_off)
    const int brow = (lane & 7) + ((lane >> 4) & 1) * 8;
    const int bcol = ((lane >> 3) & 1) * 16;
    uint32_t k_off[4], v_off[8];
#pragma unroll
    for (int nfb = 0; nfb < 4; ++nfb)
        k_off[nfb] = KH_OFF + (uint32_t)((nfb * 16 + brow) * 272 + bcol);
#pragma unroll
    for (int nfb = 0; nfb < 8; ++nfb)
        v_off[nfb] = VH_OFF + (uint32_t)((nfb * 16 + brow) * 144 + bcol);

    auto issue = [&](int st, int kv0) {
        const uint32_t s = sb + (uint32_t)st * FSTAGE;
#pragma unroll
        for (int i = 0; i < 4; ++i) {
            const int idx = tid + i * 256;
            {   // K tile: 64 rows (s) x 128 d; pitch 272B
                const int r = idx >> 4, c = idx & 15;
                CP16(s + KH_OFF + (uint32_t)(r * 272 + c * 16),
                     Kh + (size_t)(kv0 + r) * ND + c * 8);
            }
            {   // V tile: 128 rows (d) x 64 s; pitch 144B
                const int r = idx >> 3, c = idx & 7;
                CP16(s + VH_OFF + (uint32_t)(r * 144 + c * 16),
                     Vh + (size_t)r * NS + kv0 + c * 8);
            }
        }
    };

    float oacc[16][4];
#pragma unroll
    for (int i = 0; i < 16; ++i)
#pragma unroll
        for (int q = 0; q < 4; ++q) oacc[i][q] = 0.0f;
    float m0 = -1e30f, m1 = -1e30f, l0 = 0.0f, l1 = 0.0f;

    issue(0, 0);   CP_COMMIT();
    issue(1, 64);  CP_COMMIT();

    int cs = 0, ws = 2;
    for (int t = 0; t < 16; ++t) {
        if (t + 1 < 16) CP_WAIT1(); else CP_WAIT0();
        __syncthreads();

        const uint32_t stg = sb + (uint32_t)cs * FSTAGE;

        float sacc[8][4];
#pragma unroll
        for (int nf = 0; nf < 8; ++nf)
#pragma unroll
            for (int q = 0; q < 4; ++q) sacc[nf][q] = 0.0f;

        // ---- S = Q·K^T : ldsm.x4 per (nfb, kc) covers 2 n-frags ----
#pragma unroll
        for (int nfb = 0; nfb < 4; ++nfb)
#pragma unroll
            for (int kc = 0; kc < 8; ++kc) {
                uint32_t bh[4];
                ldsm4(bh, stg + k_off[nfb] + kc * 32);
                mma16816(sacc[nfb * 2],     qh[kc], bh[0], bh[1]);
                mma16816(sacc[nfb * 2],     ql[kc], bh[0], bh[1]);
                mma16816(sacc[nfb * 2 + 1], qh[kc], bh[2], bh[3]);
                mma16816(sacc[nfb * 2 + 1], ql[kc], bh[2], bh[3]);
            }

        float rm0 = -1e30f, rm1 = -1e30f;
#pragma unroll
        for (int nf = 0; nf < 8; ++nf) {
            sacc[nf][0] *= SCL2; sacc[nf][1] *= SCL2;
            sacc[nf][2] *= SCL2; sacc[nf][3] *= SCL2;
            rm0 = fmaxf(rm0, fmaxf(sacc[nf][0], sacc[nf][1]));
            rm1 = fmaxf(rm1, fmaxf(sacc[nf][2], sacc[nf][3]));
        }
        rm0 = fmaxf(rm0, __shfl_xor_sync(0xffffffffu, rm0, 1));
        rm0 = fmaxf(rm0, __shfl_xor_sync(0xffffffffu, rm0, 2));
        rm1 = fmaxf(rm1, __shfl_xor_sync(0xffffffffu, rm1, 1));
        rm1 = fmaxf(rm1, __shfl_xor_sync(0xffffffffu, rm1, 2));

        const float mn0 = fmaxf(m0, rm0), mn1 = fmaxf(m1, rm1);
        const float al0 = exp2f(m0 - mn0), al1 = exp2f(m1 - mn1);
        m0 = mn0; m1 = mn1;

        float sum0 = 0.0f, sum1 = 0.0f;
#pragma unroll
        for (int nf = 0; nf < 8; ++nf) {
            sacc[nf][0] = exp2f(sacc[nf][0] - m0);
            sacc[nf][1] = exp2f(sacc[nf][1] - m0);
            sacc[nf][2] = exp2f(sacc[nf][2] - m1);
            sacc[nf][3] = exp2f(sacc[nf][3] - m1);
            sum0 += sacc[nf][0] + sacc[nf][1];
            sum1 += sacc[nf][2] + sacc[nf][3];
        }
        sum0 += __shfl_xor_sync(0xffffffffu, sum0, 1);
        sum0 += __shfl_xor_sync(0xffffffffu, sum0, 2);
        sum1 += __shfl_xor_sync(0xffffffffu, sum1, 1);
        sum1 += __shfl_xor_sync(0xffffffffu, sum1, 2);
        l0 = l0 * al0 + sum0;
        l1 = l1 * al1 + sum1;

#pragma unroll
        for (int nf = 0; nf < 16; ++nf) {
            oacc[nf][0] *= al0; oacc[nf][1] *= al0;
            oacc[nf][2] *= al1; oacc[nf][3] *= al1;
        }

        // ---- O += P·V : ldsm.x4 per (kc, nfb) covers 2 n-frags ----
#pragma unroll
        for (int kc = 0; kc < 4; ++kc) {
            uint32_t ph[4];
            ph[0] = pk(__float2half_rn(sacc[2 * kc][0]),     __float2half_rn(sacc[2 * kc][1]));
            ph[1] = pk(__float2half_rn(sacc[2 * kc][2]),     __float2half_rn(sacc[2 * kc][3]));
            ph[2] = pk(__float2half_rn(sacc[2 * kc + 1][0]), __float2half_rn(sacc[2 * kc + 1][1]));
            ph[3] = pk(__float2half_rn(sacc[2 * kc + 1][2]), __float2half_rn(sacc[2 * kc + 1][3]));
#pragma unroll
            for (int nfb = 0; nfb < 8; ++nfb) {
                uint32_t vb[4];
                ldsm4(vb, stg + v_off[nfb] + kc * 32);
                mma16816(oacc[nfb * 2],     ph, vb[0], vb[1]);
                mma16816(oacc[nfb * 2 + 1], ph, vb[2], vb[3]);
            }
        }

        if (t + 2 < 16) { issue(ws, (t + 2) * 64); CP_COMMIT(); }
        if (++cs == 3) cs = 0;
        if (++ws == 3) ws = 0;
    }

    // ---- epilogue: normalize, store ctx hi-only ----
    const float inv0 = 1.0f / l0, inv1 = 1.0f / l1;
    const int b = bz >> 4, h = bz & 15;
    const size_t base = ((size_t)(b * NS + q0)) * NE + h * ND;
#pragma unroll
    for (int nf = 0; nf < 16; ++nf) {
        const int d = nf * 8 + tig * 2;
        *(uint32_t*)(g_ch + base + d) =
            pk(__float2half_rn(oacc[nf][0] * inv0), __float2half_rn(oacc[nf][1] * inv0));
        *(uint32_t*)(g_ch + base + 8 * NE + d) =
            pk(__float2half_rn(oacc[nf][2] * inv1), __float2half_rn(oacc[nf][3] * inv1));
    }
}

// ---------------- fp32 -> fp16 conversion (hi only) ---------------------------
__global__ __launch_bounds__(256) void cvt_k(const float4* __restrict__ src,
                                             int n4, int sel)
{
    const int i = blockIdx.x * 256 + threadIdx.x;
    if (i >= n4) return;
    const float4 v = src[i];
    hf* dst = sel == 0 ? g_xh : sel == 1 ? g_wih : g_woh;
    ((uint2*)dst)[i] = make_uint2(
        pk(__float2half_rn(v.x), __float2half_rn(v.y)),
        pk(__float2half_rn(v.z), __float2half_rn(v.w)));
}

// ---------------- host --------------------------------------------------------
extern "C" void kernel_launch(void* const* d_in, const int* in_sizes, int n_in,
                              void* d_out, int out_size)
{
    (void)in_sizes; (void)n_in; (void)out_size;
    const float* x  = (const float*)d_in[0];
    const float* wi = (const float*)d_in[1];
    const float* bi = (const float*)d_in[2];
    const float* wo = (const float*)d_in[3];
    const float* bo = (const float*)d_in[4];
    float* out = (float*)d_out;

    cudaFuncSetAttribute(gemm_mma<PQkv>, cudaFuncAttributeMaxDynamicSharedMemorySize, GSMEM);
    cudaFuncSetAttribute(gemm_mma<POut>, cudaFuncAttributeMaxDynamicSharedMemorySize, GSMEM);
    cudaFuncSetAttribute(flash_attn,     cudaFuncAttributeMaxDynamicSharedMemorySize, FSMEM);

    // 0) convert external fp32 operands to fp16 (all hi-only)
    cvt_k<<<(NB*NS*NE/4 + 255) / 256, 256>>>((const float4*)x,  NB*NS*NE/4, 0);
    cvt_k<<<(3*NE*NE/4  + 255) / 256, 256>>>((const float4*)wi, 3*NE*NE/4,  1);
    cvt_k<<<(NE*NE/4    + 255) / 256, 256>>>((const float4*)wo, NE*NE/4,    2);

    // 1) QKV projection (+bias, head scatter, V transposed)
    gemm_mma<PQkv><<<dim3(48, 32, 1), 256, GSMEM>>>(PQkv{bi}, NE);

    // 2-4) fused attention: scores + softmax + P·V
    flash_attn<<<dim3(NS / 128, NB * NH), 256, FSMEM>>>();

    // 5) out = ctx W_out^T + bias
    gemm_mma<POut><<<dim3(16, 32, 1), 256, GSMEM>>>(POut{bo, out}, NE);
}